// round 5
// baseline (speedup 1.0000x reference)
#include <cuda_runtime.h>

#define HW 16384
#define TILE_W 32
#define TILE_H 16
#define XSTR 34            // even padded row stride (8B-aligned pairs)
#define CSTR 612           // 18 * 34
#define XT_SZ_H 19584      // 32 channels * 612

typedef unsigned long long ull;

// ---------------- f32x2 helpers ------------------------------------------------
__device__ __forceinline__ ull pk2(float lo, float hi) {
    ull r; asm("mov.b64 %0,{%1,%2};" : "=l"(r) : "f"(lo), "f"(hi)); return r;
}
__device__ __forceinline__ ull dup2(float v) { return pk2(v, v); }
__device__ __forceinline__ void upk2(ull v, float& lo, float& hi) {
    asm("mov.b64 {%0,%1},%2;" : "=f"(lo), "=f"(hi) : "l"(v));
}
__device__ __forceinline__ ull f2fma(ull a, ull b, ull c) {
    ull d; asm("fma.rn.f32x2 %0,%1,%2,%3;" : "=l"(d) : "l"(a), "l"(b), "l"(c)); return d;
}
__device__ __forceinline__ ull f2add(ull a, ull b) {
    ull d; asm("add.rn.f32x2 %0,%1,%2;" : "=l"(d) : "l"(a), "l"(b)); return d;
}
__device__ __forceinline__ ull f2relu(ull v) {
    float lo, hi; upk2(v, lo, hi);
    return pk2(fmaxf(lo, 0.f), fmaxf(hi, 0.f));
}

// ---------------- scratch ----------------------------------------------------
__device__ float g_wraw[8 * 72 * HW];
__device__ float g_xv[8 * 64 * HW];
__device__ float g_gnpart[256 * 16];
__device__ float g_gnstat[64 * 2];
__device__ float g_chanpart[256 * 64];
__device__ float g_yscale[512];

__constant__ float c_gnw[72], c_gnb[72], c_wdu1[256], c_wdu2[256];

// ---------------- passA smem layout (float offsets), per half ----------------
// WKd : oc-PAIRED key weights [(g4*8+ci)*4+ocp][t] pairs (w_oc0[t], w_oc1[t])
// WE1d: dup quads [m][o][4] = (wx,wx,wk,wk)
// WE2d: dup quads [o2l][icp][4] = (w_ic0,w_ic0,w_ic1,w_ic1)
// WC1d: dup quads [oc][icp][4]
#define WKd  0             // 2304
#define WE1d 2304          // 2048
#define WE2d 4352          // 1152
#define BE2  5504          // 40
#define WC1d 5544          // 2048
#define XTA  7592
#define SMEMA ((XTA + XT_SZ_H) * 4)

__global__ void __launch_bounds__(256, 2) passA(
    const float* __restrict__ x, const float* __restrict__ wkey,
    const float* __restrict__ we1, const float* __restrict__ we2,
    const float* __restrict__ be2, const float* __restrict__ wc1)
{
    extern __shared__ float sm[];
    const int tid = threadIdx.x;
    const int b = blockIdx.z >> 1, half = blockIdx.z & 1;

    // key weights, oc-pair interleaved
    for (int i = tid; i < 2304; i += 256) {
        int w18 = i / 18, r = i - w18 * 18;
        int t = r >> 1, s = r & 1;
        int ocp = w18 & 3, gci = w18 >> 2;      // gci = g4*8+ci
        int ci = gci & 7, g4 = gci >> 3;
        sm[WKd + i] = wkey[(half * 32 + g4 * 8 + ocp * 2 + s) * 72 + ci * 9 + t];
    }
    // e1 dup quads
    for (int i = tid; i < 2048; i += 256) {
        int q = i & 3, o = (i >> 2) & 15, m = i >> 6;
        sm[WE1d + i] = we1[half * 1024 + o * 64 + m * 2 + (q >> 1)];
    }
    // e2 dup quads
    for (int i = tid; i < 1152; i += 256) {
        int q = i & 3, icp = (i >> 2) & 7, o2l = i >> 5;
        sm[WE2d + i] = we2[half * 576 + o2l * 16 + icp * 2 + (q >> 1)];
    }
    if (tid < 36) sm[BE2 + tid] = be2[half * 36 + tid];
    // wc1 dup quads
    for (int i = tid; i < 2048; i += 256) {
        int q = i & 3, icp = (i >> 2) & 15, oc = i >> 6;
        sm[WC1d + i] = wc1[half * 1024 + oc * 32 + icp * 2 + (q >> 1)];
    }

    const int ty0 = blockIdx.y * TILE_H, tx0 = blockIdx.x * TILE_W;
    const float* xb = x + (size_t)b * 64 * HW + ((size_t)half << 19);
    float* xt = sm + XTA;

    for (int i = tid; i < XT_SZ_H; i += 256) {
        int c = i / CSTR, r = i - c * CSTR, yy = r / XSTR, xx = r - yy * XSTR;
        int gy = ty0 + yy - 1, gx = tx0 + xx - 1;
        float v = 0.f;
        if ((unsigned)gy < 128u && (unsigned)gx < 128u)
            v = __ldg(xb + (c << 14) + (gy << 7) + gx);
        xt[i] = v;
    }
    __syncthreads();

    const int lty = tid >> 4, lx0 = (tid & 15) << 1;
    const int pix = ((ty0 + lty) << 7) + tx0 + lx0;

    ull acc2[16];
    #pragma unroll
    for (int o = 0; o < 16; o++) acc2[o] = 0ull;

    #pragma unroll 1
    for (int g4 = 0; g4 < 4; g4++) {
        // kk2[ocp]  : (k_oc0,k_oc1) for pixel0 ; kk2[4+ocp] for pixel1
        ull kk2[8];
        #pragma unroll
        for (int i = 0; i < 8; i++) kk2[i] = 0ull;

        #pragma unroll 1
        for (int ci = 0; ci < 8; ci++) {
            const float* pb = xt + (g4 * 8 + ci) * CSTR + lty * XSTR + lx0;
            ull dp[12];
            #pragma unroll
            for (int dy = 0; dy < 3; dy++) {
                ull A = *(const ull*)(pb + dy * XSTR);
                ull B = *(const ull*)(pb + dy * XSTR + 2);
                float p0, p1, p2, p3;
                upk2(A, p0, p1); upk2(B, p2, p3);
                dp[dy * 4 + 0] = dup2(p0); dp[dy * 4 + 1] = dup2(p1);
                dp[dy * 4 + 2] = dup2(p2); dp[dy * 4 + 3] = dup2(p3);
            }
            const ull* wd = (const ull*)(sm + WKd) + (g4 * 8 + ci) * 36;
            #pragma unroll
            for (int ocp = 0; ocp < 4; ocp++) {
                ull kA = kk2[ocp], kB = kk2[4 + ocp];
                #pragma unroll
                for (int dy = 0; dy < 3; dy++)
                    #pragma unroll
                    for (int dx = 0; dx < 3; dx++) {
                        ull w = wd[ocp * 9 + dy * 3 + dx];
                        kA = f2fma(dp[dy * 4 + dx],     w, kA);
                        kB = f2fma(dp[dy * 4 + dx + 1], w, kB);
                    }
                kk2[ocp] = kA; kk2[4 + ocp] = kB;
            }
        }
        // repack: kv2[ci] = (relu k_px0[ci], relu k_px1[ci])
        float k0[8], k1[8];
        #pragma unroll
        for (int ocp = 0; ocp < 4; ocp++) {
            upk2(kk2[ocp],     k0[2 * ocp], k0[2 * ocp + 1]);
            upk2(kk2[4 + ocp], k1[2 * ocp], k1[2 * ocp + 1]);
        }
        // e1 contributions
        #pragma unroll 1
        for (int ci = 0; ci < 8; ci++) {
            const float* ctr = xt + (g4 * 8 + ci) * CSTR + (lty + 1) * XSTR + lx0 + 1;
            ull xc2 = pk2(ctr[0], ctr[1]);
            ull kv2 = pk2(fmaxf(k0[ci], 0.f), fmaxf(k1[ci], 0.f));
            const ulonglong2* w1 = (const ulonglong2*)(sm + WE1d + ((g4 * 8 + ci) << 6));
            #pragma unroll
            for (int o = 0; o < 16; o++) {
                ulonglong2 w = w1[o];
                acc2[o] = f2fma(xc2, w.x, f2fma(kv2, w.y, acc2[o]));
            }
        }
    }
    #pragma unroll
    for (int o = 0; o < 16; o++) acc2[o] = f2relu(acc2[o]);

    // e2 + GN partials + wraw store
    float lsum[4], lsq[4];
    #pragma unroll
    for (int g4 = 0; g4 < 4; g4++) {
        ull s2 = 0ull, q2 = 0ull;
        #pragma unroll
        for (int j = 0; j < 9; j++) {
            const int o2l = g4 * 9 + j;
            const ulonglong2* w2 = (const ulonglong2*)(sm + WE2d + (o2l << 5));
            ull a2 = dup2(sm[BE2 + o2l]);
            #pragma unroll
            for (int icp = 0; icp < 8; icp++) {
                ulonglong2 w = w2[icp];
                a2 = f2fma(acc2[icp * 2],     w.x, a2);
                a2 = f2fma(acc2[icp * 2 + 1], w.y, a2);
            }
            *(ull*)(g_wraw + (((size_t)b * 72 + half * 36 + o2l) << 14) + pix) = a2;
            s2 = f2add(s2, a2);
            q2 = f2fma(a2, a2, q2);
        }
        float slo, shi, qlo, qhi;
        upk2(s2, slo, shi); upk2(q2, qlo, qhi);
        lsum[g4] = slo + shi; lsq[g4] = qlo + qhi;
    }

    // xv = grouped conv1x1
    {
        ull xin2[32];
        #pragma unroll
        for (int ic = 0; ic < 32; ic++) {
            const float* ctr = xt + ic * CSTR + (lty + 1) * XSTR + lx0 + 1;
            xin2[ic] = pk2(ctr[0], ctr[1]);
        }
        #pragma unroll 1
        for (int oc = 0; oc < 32; oc++) {
            const ulonglong2* w = (const ulonglong2*)(sm + WC1d + (oc << 6));
            ull a2 = 0ull;
            #pragma unroll
            for (int icp = 0; icp < 16; icp++) {
                ulonglong2 wv = w[icp];
                a2 = f2fma(xin2[icp * 2],     wv.x, a2);
                a2 = f2fma(xin2[icp * 2 + 1], wv.y, a2);
            }
            *(ull*)(g_xv + (((size_t)b * 64 + half * 32 + oc) << 14) + pix) = a2;
        }
    }

    // GN partial reduce
    __syncthreads();
    #pragma unroll
    for (int off = 16; off; off >>= 1)
        #pragma unroll
        for (int g4 = 0; g4 < 4; g4++) {
            lsum[g4] += __shfl_xor_sync(0xffffffffu, lsum[g4], off);
            lsq[g4]  += __shfl_xor_sync(0xffffffffu, lsq[g4],  off);
        }
    const int wid = tid >> 5, lane = tid & 31;
    if (lane == 0) {
        #pragma unroll
        for (int g4 = 0; g4 < 4; g4++) {
            sm[wid * 8 + g4] = lsum[g4];
            sm[wid * 8 + 4 + g4] = lsq[g4];
        }
    }
    __syncthreads();
    if (tid < 8) {
        float s = 0.f;
        #pragma unroll
        for (int w = 0; w < 8; w++) s += sm[w * 8 + tid];
        int slot = (b * 32 + blockIdx.y * 4 + blockIdx.x) * 16;
        int e = (tid < 4) ? (half * 4 + tid) : (8 + half * 4 + tid - 4);
        g_gnpart[slot + e] = s;
    }
}

// ---------------- GN stats (parallel) ----------------------------------------
__global__ void statsK()
{
    int tid = threadIdx.x;
    int idx = tid >> 3, k = tid & 7;
    int b = idx >> 3, gg = idx & 7;
    float s = 0.f, q = 0.f;
    #pragma unroll
    for (int t = 0; t < 4; t++) {
        int tile = k * 4 + t;
        s += g_gnpart[(b * 32 + tile) * 16 + gg];
        q += g_gnpart[(b * 32 + tile) * 16 + 8 + gg];
    }
    #pragma unroll
    for (int off = 4; off; off >>= 1) {
        s += __shfl_xor_sync(0xffffffffu, s, off);
        q += __shfl_xor_sync(0xffffffffu, q, off);
    }
    if (k == 0) {
        const float inv_n = 1.f / 147456.f;
        float m = s * inv_n;
        float v = fmaf(q, inv_n, -m * m);
        g_gnstat[idx * 2] = m;
        g_gnstat[idx * 2 + 1] = rsqrtf(v + 1e-5f);
    }
}

// ---------------- passB (half-split, FMA2) -------------------------------------
#define ST  0
#define SC  8
#define XTB 264
#define SMEMB ((XTB + XT_SZ_H) * 4)

__global__ void __launch_bounds__(256, 2) passB(float* __restrict__ out)
{
    extern __shared__ float sm[];
    const int tid = threadIdx.x;
    const int b = blockIdx.z >> 1, half = blockIdx.z & 1;
    const int ty0 = blockIdx.y * TILE_H, tx0 = blockIdx.x * TILE_W;

    if (tid < 8) sm[ST + tid] = g_gnstat[b * 16 + half * 8 + tid];
    if (tid < 256) sm[SC + tid] = 0.f;

    float* xt = sm + XTB;
    const float* xvb = g_xv + (size_t)b * 64 * HW + ((size_t)half << 19);
    for (int i = tid; i < XT_SZ_H; i += 256) {
        int c = i / CSTR, r = i - c * CSTR, yy = r / XSTR, xx = r - yy * XSTR;
        int gy = ty0 + yy - 1, gx = tx0 + xx - 1;
        float v = 0.f;
        if ((unsigned)gy < 128u && (unsigned)gx < 128u)
            v = __ldg(xvb + (c << 14) + (gy << 7) + gx);
        xt[i] = v;
    }
    __syncthreads();

    const int lty = tid >> 4, lx0 = (tid & 15) << 1;
    const int pix = ((ty0 + lty) << 7) + tx0 + lx0;
    const int wid = tid >> 5;

    #pragma unroll
    for (int g4 = 0; g4 < 4; g4++) {
        float mean = sm[ST + g4 * 2], rstd = sm[ST + g4 * 2 + 1];
        ull bw[9];
        #pragma unroll
        for (int t = 0; t < 9; t++) {
            int o2 = half * 36 + g4 * 9 + t;
            float2 raw = *(const float2*)(g_wraw + (((size_t)b * 72 + o2) << 14) + pix);
            float w0 = fmaf((raw.x - mean) * rstd, c_gnw[o2], c_gnb[o2]);
            float w1 = fmaf((raw.y - mean) * rstd, c_gnw[o2], c_gnb[o2]);
            bw[t] = pk2(w0, w1);
        }
        #pragma unroll 1
        for (int cc = 0; cc < 8; cc++) {
            int cl = g4 * 8 + cc;
            const float* pb = xt + cl * CSTR + lty * XSTR + lx0;
            ull a2 = 0ull;
            #pragma unroll
            for (int dy = 0; dy < 3; dy++) {
                ull A = *(const ull*)(pb + dy * XSTR);
                ull B = *(const ull*)(pb + dy * XSTR + 2);
                float p0, p1, p2, p3;
                upk2(A, p0, p1); upk2(B, p2, p3);
                a2 = f2fma(A,           bw[dy * 3 + 0], a2);
                a2 = f2fma(pk2(p1, p2), bw[dy * 3 + 1], a2);
                a2 = f2fma(B,           bw[dy * 3 + 2], a2);
            }
            *(ull*)(out + (((size_t)b * 64 + half * 32 + cl) << 14) + pix) = a2;
            float a0, a1; upk2(a2, a0, a1);
            float s = a0 + a1;
            #pragma unroll
            for (int off = 16; off; off >>= 1)
                s += __shfl_xor_sync(0xffffffffu, s, off);
            if ((tid & 31) == 0) sm[SC + wid * 32 + cl] += s;
        }
    }
    __syncthreads();
    if (tid < 32) {
        float s = 0.f;
        #pragma unroll
        for (int w = 0; w < 8; w++) s += sm[SC + w * 32 + tid];
        g_chanpart[(b * 32 + blockIdx.y * 4 + blockIdx.x) * 64 + half * 32 + tid] = s;
    }
}

// ---------------- attention -----------------------------------------------------
__global__ void attnK()
{
    int b = blockIdx.x, tid = threadIdx.x;
    int c = tid >> 3, k = tid & 7;
    __shared__ float m[64], t4[4];
    float s = 0.f;
    #pragma unroll
    for (int t = 0; t < 4; t++)
        s += g_chanpart[(b * 32 + k * 4 + t) * 64 + c];
    #pragma unroll
    for (int off = 4; off; off >>= 1)
        s += __shfl_xor_sync(0xffffffffu, s, off);
    if (k == 0) m[c] = s * (1.f / 16384.f);
    __syncthreads();
    if (tid < 4) {
        float a = 0.f;
        for (int i = 0; i < 64; i++) a = fmaf(m[i], c_wdu1[tid * 64 + i], a);
        t4[tid] = fmaxf(a, 0.f);
    }
    __syncthreads();
    if (tid < 64) {
        float a = 0.f;
        #pragma unroll
        for (int j = 0; j < 4; j++) a = fmaf(t4[j], c_wdu2[tid * 4 + j], a);
        g_yscale[b * 64 + tid] = 1.f / (1.f + expf(-a));
    }
}

// ---------------- final scale -----------------------------------------------------
__global__ void scaleK(float* __restrict__ out)
{
    int i = blockIdx.x * blockDim.x + threadIdx.x;
    float4* p = (float4*)out;
    float s = g_yscale[i >> 12];
    float4 v = p[i];
    v.x *= s; v.y *= s; v.z *= s; v.w *= s;
    p[i] = v;
}

// ---------------- launcher ---------------------------------------------------------
extern "C" void kernel_launch(void* const* d_in, const int* in_sizes, int n_in,
                              void* d_out, int out_size)
{
    const float* x    = (const float*)d_in[0];
    const float* wkey = (const float*)d_in[1];
    const float* we1  = (const float*)d_in[2];
    const float* we2  = (const float*)d_in[3];
    const float* be2  = (const float*)d_in[4];
    const float* gnw  = (const float*)d_in[5];
    const float* gnb  = (const float*)d_in[6];
    const float* wc1  = (const float*)d_in[7];
    const float* wdu1 = (const float*)d_in[8];
    const float* wdu2 = (const float*)d_in[9];
    float* out = (float*)d_out;

    cudaMemcpyToSymbolAsync(c_gnw,  gnw,  72 * 4,  0, cudaMemcpyDeviceToDevice, 0);
    cudaMemcpyToSymbolAsync(c_gnb,  gnb,  72 * 4,  0, cudaMemcpyDeviceToDevice, 0);
    cudaMemcpyToSymbolAsync(c_wdu1, wdu1, 256 * 4, 0, cudaMemcpyDeviceToDevice, 0);
    cudaMemcpyToSymbolAsync(c_wdu2, wdu2, 256 * 4, 0, cudaMemcpyDeviceToDevice, 0);

    cudaFuncSetAttribute(passA, cudaFuncAttributeMaxDynamicSharedMemorySize, SMEMA);
    cudaFuncSetAttribute(passB, cudaFuncAttributeMaxDynamicSharedMemorySize, SMEMB);

    dim3 grid(4, 8, 16);
    passA<<<grid, 256, SMEMA>>>(x, wkey, we1, we2, be2, wc1);
    statsK<<<1, 512>>>();
    passB<<<grid, 256, SMEMB>>>(out);
    attnK<<<8, 512>>>();
    scaleK<<<8192, 256>>>(out);
}